// round 8
// baseline (speedup 1.0000x reference)
#include <cuda_runtime.h>
#include <cstdint>

#define B_   32
#define S_   2048
#define IN_  300
#define H_   16
#define D_   16
#define A_   64
#define NIT  20
#define GRAV 0.01f

#define NPTS  (B_ * S_)    // 65536
#define NBLK  256          // main blocks: 128 thr, 2 points/thread -> 256 pts/blk

typedef unsigned long long u64;

// ---- packed f32x2 helpers (sm_103a FFMA2 path) ----
__device__ __forceinline__ u64 pack2(float lo, float hi) {
    u64 r; asm("mov.b64 %0, {%1,%2};" : "=l"(r) : "f"(lo), "f"(hi)); return r;
}
__device__ __forceinline__ void unpack2(u64 v, float& lo, float& hi) {
    asm("mov.b64 {%0,%1}, %2;" : "=f"(lo), "=f"(hi) : "l"(v));
}
__device__ __forceinline__ u64 ffma2(u64 a, u64 b, u64 c) {
    u64 d; asm("fma.rn.f32x2 %0, %1, %2, %3;" : "=l"(d) : "l"(a), "l"(b), "l"(c)); return d;
}
__device__ __forceinline__ u64 fmul2(u64 a, u64 b) {
    u64 d; asm("mul.rn.f32x2 %0, %1, %2;" : "=l"(d) : "l"(a), "l"(b)); return d;
}
__device__ __forceinline__ float sqrt_ap(float x) {
    float r; asm("sqrt.approx.f32 %0, %1;" : "=f"(r) : "f"(x)); return r;
}
__device__ __forceinline__ float rcp_ap(float x) {
    float r; asm("rcp.approx.f32 %0, %1;" : "=f"(r) : "f"(x)); return r;
}

// ---- scratch (device globals: no allocs allowed) ----
__device__ float g_afp[NBLK * D_];   // per-block partial sums of final positions
__device__ float g_chgp[NBLK];       // per-block partial of squared last-iter deltas
__device__ float g_rec[B_ * IN_];    // decoder output per b

// encoder layer-1 step for one input scalar (both points share weights)
#define ENC4(xa, xb, w0, w1, w2, w3) do {                                   \
    u64 xa2 = pack2(xa, xa), xb2 = pack2(xb, xb);                           \
    accA[0]=ffma2(xa2,(w0).x,accA[0]); accB[0]=ffma2(xb2,(w0).x,accB[0]);   \
    accA[1]=ffma2(xa2,(w0).y,accA[1]); accB[1]=ffma2(xb2,(w0).y,accB[1]);   \
    accA[2]=ffma2(xa2,(w1).x,accA[2]); accB[2]=ffma2(xb2,(w1).x,accB[2]);   \
    accA[3]=ffma2(xa2,(w1).y,accA[3]); accB[3]=ffma2(xb2,(w1).y,accB[3]);   \
    accA[4]=ffma2(xa2,(w2).x,accA[4]); accB[4]=ffma2(xb2,(w2).x,accB[4]);   \
    accA[5]=ffma2(xa2,(w2).y,accA[5]); accB[5]=ffma2(xb2,(w2).y,accB[5]);   \
    accA[6]=ffma2(xa2,(w3).x,accA[6]); accB[6]=ffma2(xb2,(w3).x,accB[6]);   \
    accA[7]=ffma2(xa2,(w3).y,accA[7]); accB[7]=ffma2(xb2,(w3).y,accB[7]);   \
} while (0)

// ============================================================
// Fused: encoder + 20 gravity iterations + block reductions.
// 256 blocks x 128 threads (4 warps -> all SMSPs), TWO points
// per thread for ILP; per-point arithmetic identical to R3.
// ============================================================
__global__ void __launch_bounds__(128) gda_main(
    const float* __restrict__ inputs,
    const float* __restrict__ enc_w1, const float* __restrict__ enc_b1,
    const float* __restrict__ enc_w2, const float* __restrict__ enc_b2,
    const float* __restrict__ attractors)
{
    __shared__ ulonglong2 s_w1[IN_ * 4];   // 300x16 f32 = 19200B
    __shared__ ulonglong2 s_att[A_ * 4];   // 64x16 f32  = 4096B
    __shared__ float s_asq[A_];            // |a|^2
    __shared__ float s_b1[H_], s_b2[D_], s_w2[H_ * D_];
    __shared__ float s_af[D_];
    __shared__ float s_chg;

    const int tid = threadIdx.x;
    {
        float* w1f = reinterpret_cast<float*>(s_w1);
        for (int i = tid; i < IN_ * H_; i += 128) w1f[i] = enc_w1[i];
        float* af = reinterpret_cast<float*>(s_att);
        for (int i = tid; i < A_ * D_; i += 128) af[i] = attractors[i];
        for (int i = tid; i < H_ * D_; i += 128) s_w2[i] = enc_w2[i];  // BUGFIX: strided (256 > 128 threads)
        if (tid < H_)      s_b1[tid] = enc_b1[tid];
        if (tid < D_)      s_b2[tid] = enc_b2[tid];
        if (tid < D_)      s_af[tid] = 0.f;
        if (tid == 0)      s_chg = 0.f;
    }
    __syncthreads();
    if (tid < A_) {
        const float* a = reinterpret_cast<const float*>(s_att) + tid * D_;
        float q = 0.f;
        #pragma unroll
        for (int d = 0; d < D_; d++) q = fmaf(a[d], a[d], q);
        s_asq[tid] = q;
    }
    __syncthreads();

    const int pA = blockIdx.x * 256 + tid;        // point A
    const int pB = pA + 128;                      // point B

    // ---------------- encoder layer 1 (both points, shared weight loads) ----
    u64 accA[8], accB[8];
    #pragma unroll
    for (int j = 0; j < 8; j++) { accA[j] = 0ull; accB[j] = 0ull; }
    const float4* rowA = reinterpret_cast<const float4*>(inputs + (size_t)pA * IN_);
    const float4* rowB = reinterpret_cast<const float4*>(inputs + (size_t)pB * IN_);
    for (int i = 0; i < IN_ / 4; i++) {
        float4 xA = __ldg(rowA + i);
        float4 xB = __ldg(rowB + i);
        const ulonglong2* wp = s_w1 + i * 16;
        ENC4(xA.x, xB.x, wp[0],  wp[1],  wp[2],  wp[3]);
        ENC4(xA.y, xB.y, wp[4],  wp[5],  wp[6],  wp[7]);
        ENC4(xA.z, xB.z, wp[8],  wp[9],  wp[10], wp[11]);
        ENC4(xA.w, xB.w, wp[12], wp[13], wp[14], wp[15]);
    }

    // ---------------- encoder layer 2 (scalar, per point — R3 verbatim) ----
    u64 p2a[8], p2b[8];
    {
        float hvA[H_], hvB[H_];
        #pragma unroll
        for (int j = 0; j < 8; j++) {
            float lo, hi;
            unpack2(accA[j], lo, hi);
            hvA[2*j]   = fmaxf(lo + s_b1[2*j],   0.f);
            hvA[2*j+1] = fmaxf(hi + s_b1[2*j+1], 0.f);
            unpack2(accB[j], lo, hi);
            hvB[2*j]   = fmaxf(lo + s_b1[2*j],   0.f);
            hvB[2*j+1] = fmaxf(hi + s_b1[2*j+1], 0.f);
        }
        #pragma unroll
        for (int d = 0; d < D_; d += 2) {
            float a0 = s_b2[d], a1 = s_b2[d+1];
            float b0 = s_b2[d], b1 = s_b2[d+1];
            #pragma unroll
            for (int h = 0; h < H_; h++) {
                float w0 = s_w2[h * D_ + d], w1 = s_w2[h * D_ + d + 1];
                a0 = fmaf(hvA[h], w0, a0);  a1 = fmaf(hvA[h], w1, a1);
                b0 = fmaf(hvB[h], w0, b0);  b1 = fmaf(hvB[h], w1, b1);
            }
            p2a[d >> 1] = pack2(a0, a1);
            p2b[d >> 1] = pack2(b0, b1);
        }
    }

    // ---------------- gravity: 20 iterations, 2 points interleaved ----
    const u64 k01   = pack2(0.1f, 0.1f);
    const u64 kneg1 = pack2(-1.f, -1.f);
    float chg = 0.f;

    for (int it = 0; it < NIT; it++) {
        u64 qa = fmul2(p2a[0], p2a[0]);
        u64 qb = fmul2(p2b[0], p2b[0]);
        #pragma unroll
        for (int j = 1; j < 8; j++) {
            qa = ffma2(p2a[j], p2a[j], qa);
            qb = ffma2(p2b[j], p2b[j], qb);
        }
        float l0, h0, l1, h1;
        unpack2(qa, l0, h0); unpack2(qb, l1, h1);
        const float psqA = l0 + h0;
        const float psqB = l1 + h1;

        u64 faA[8], faB[8];
        #pragma unroll
        for (int j = 0; j < 8; j++) { faA[j] = 0ull; faB[j] = 0ull; }
        float wsA0 = 0.f, wsA1 = 0.f, wsB0 = 0.f, wsB1 = 0.f;

        #pragma unroll 2
        for (int a = 0; a < A_; a++) {
            const ulonglong2* av = s_att + a * 4;
            ulonglong2 v0 = av[0], v1 = av[1], v2 = av[2], v3 = av[3];
            // two independent 8-deep dot chains (per-point order == R3)
            u64 dA = fmul2(p2a[0], v0.x);
            u64 dB = fmul2(p2b[0], v0.x);
            dA = ffma2(p2a[1], v0.y, dA);  dB = ffma2(p2b[1], v0.y, dB);
            dA = ffma2(p2a[2], v1.x, dA);  dB = ffma2(p2b[2], v1.x, dB);
            dA = ffma2(p2a[3], v1.y, dA);  dB = ffma2(p2b[3], v1.y, dB);
            dA = ffma2(p2a[4], v2.x, dA);  dB = ffma2(p2b[4], v2.x, dB);
            dA = ffma2(p2a[5], v2.y, dA);  dB = ffma2(p2b[5], v2.y, dB);
            dA = ffma2(p2a[6], v3.x, dA);  dB = ffma2(p2b[6], v3.x, dB);
            dA = ffma2(p2a[7], v3.y, dA);  dB = ffma2(p2b[7], v3.y, dB);
            float aql, aqh, bql, bqh;
            unpack2(dA, aql, aqh); unpack2(dB, bql, bqh);
            const float asq = s_asq[a];
            float sA = fmaf(-2.f, aql + aqh, psqA + asq);
            float sB = fmaf(-2.f, bql + bqh, psqB + asq);
            sA = fmaxf(sA, 1e-12f);
            sB = fmaxf(sB, 1e-12f);
            float distA = sqrt_ap(sA) + 1e-6f;        // EXACT validated form
            float distB = sqrt_ap(sB) + 1e-6f;
            float wA = GRAV * rcp_ap(distA * distA);
            float wB = GRAV * rcp_ap(distB * distB);
            if (a & 1) { wsA1 += wA; wsB1 += wB; } else { wsA0 += wA; wsB0 += wB; }
            u64 wvA = pack2(wA, wA), wvB = pack2(wB, wB);
            faA[0] = ffma2(wvA, v0.x, faA[0]);  faB[0] = ffma2(wvB, v0.x, faB[0]);
            faA[1] = ffma2(wvA, v0.y, faA[1]);  faB[1] = ffma2(wvB, v0.y, faB[1]);
            faA[2] = ffma2(wvA, v1.x, faA[2]);  faB[2] = ffma2(wvB, v1.x, faB[2]);
            faA[3] = ffma2(wvA, v1.y, faA[3]);  faB[3] = ffma2(wvB, v1.y, faB[3]);
            faA[4] = ffma2(wvA, v2.x, faA[4]);  faB[4] = ffma2(wvB, v2.x, faB[4]);
            faA[5] = ffma2(wvA, v2.y, faA[5]);  faB[5] = ffma2(wvB, v2.y, faB[5]);
            faA[6] = ffma2(wvA, v3.x, faA[6]);  faB[6] = ffma2(wvB, v3.x, faB[6]);
            faA[7] = ffma2(wvA, v3.y, faA[7]);  faB[7] = ffma2(wvB, v3.y, faB[7]);
        }

        const float cA = fmaf(-0.1f, wsA0 + wsA1, 1.0f);
        const float cB = fmaf(-0.1f, wsB0 + wsB1, 1.0f);
        const u64 c2A = pack2(cA, cA);
        const u64 c2B = pack2(cB, cB);
        if (it == NIT - 1) {
            u64 chA = 0ull, chB = 0ull;
            #pragma unroll
            for (int j = 0; j < 8; j++) {
                u64 npA = ffma2(p2a[j], c2A, fmul2(faA[j], k01));
                u64 npB = ffma2(p2b[j], c2B, fmul2(faB[j], k01));
                u64 dlA = ffma2(p2a[j], kneg1, npA);
                u64 dlB = ffma2(p2b[j], kneg1, npB);
                chA = ffma2(dlA, dlA, chA);
                chB = ffma2(dlB, dlB, chB);
                p2a[j] = npA;  p2b[j] = npB;
            }
            float cl, ch;
            unpack2(chA, cl, ch); chg  = cl + ch;
            unpack2(chB, cl, ch); chg += cl + ch;
        } else {
            #pragma unroll
            for (int j = 0; j < 8; j++) {
                p2a[j] = ffma2(p2a[j], c2A, fmul2(faA[j], k01));
                p2b[j] = ffma2(p2b[j], c2B, fmul2(faB[j], k01));
            }
        }
    }

    // ---------------- reductions (A+B combined per thread) ----------------
    #pragma unroll
    for (int j = 0; j < 8; j++) {
        float la, ha, lb, hb;
        unpack2(p2a[j], la, ha);
        unpack2(p2b[j], lb, hb);
        float lo = la + lb, hi = ha + hb;
        #pragma unroll
        for (int off = 16; off; off >>= 1) {
            lo += __shfl_down_sync(0xffffffffu, lo, off);
            hi += __shfl_down_sync(0xffffffffu, hi, off);
        }
        if ((tid & 31) == 0) {
            atomicAdd(&s_af[2 * j], lo);
            atomicAdd(&s_af[2 * j + 1], hi);
        }
    }
    #pragma unroll
    for (int off = 16; off; off >>= 1)
        chg += __shfl_down_sync(0xffffffffu, chg, off);
    if ((tid & 31) == 0) atomicAdd(&s_chg, chg);
    __syncthreads();

    if (tid < D_) g_afp[blockIdx.x * D_ + tid] = s_af[tid];
    if (tid == 0) g_chgp[blockIdx.x]           = s_chg;
}

// ============================================================
// Decoder: reduce block partials -> af -> relu(16) -> 300,
// masses, final_change. 32 blocks (one per batch), 320 threads.
// ============================================================
__global__ void dec_k(const float* __restrict__ dec_w1, const float* __restrict__ dec_b1,
                      const float* __restrict__ dec_w2, const float* __restrict__ dec_b2,
                      const float* __restrict__ mass_w, const float* __restrict__ mass_b,
                      float* __restrict__ out)
{
    __shared__ float af[D_], h[H_];
    const int b = blockIdx.x, t = threadIdx.x;
    const int blk0 = b * (NBLK / B_);          // 8 gda blocks per batch
    if (t < D_) {
        float v = 0.f;
        #pragma unroll
        for (int k = 0; k < NBLK / B_; k++)
            v += g_afp[(blk0 + k) * D_ + t];
        v *= (1.f / (float)S_);
        af[t] = v;
        out[b * D_ + t] = v;                   // attractor_field [B,16]
    }
    if (b == 0 && t >= 32 && t < 64) {
        const int lane = t - 32;
        float c = 0.f;
        for (int i = lane; i < NBLK; i += 32) c += g_chgp[i];
        #pragma unroll
        for (int off = 16; off; off >>= 1)
            c += __shfl_down_sync(0xffffffffu, c, off);
        if (lane == 0)
            out[B_ * D_ + B_ * S_ * IN_ + B_] = sqrtf(c);   // final_change
    }
    __syncthreads();
    if (t < H_) {
        float v = dec_b1[t];
        #pragma unroll
        for (int d = 0; d < D_; d++) v = fmaf(af[d], dec_w1[d * H_ + t], v);
        h[t] = fmaxf(v, 0.f);
    } else if (t == H_) {
        float m = mass_b[0];
        #pragma unroll
        for (int d = 0; d < D_; d++) m = fmaf(af[d], mass_w[d], m);
        out[B_ * D_ + B_ * S_ * IN_ + b] = 1.f / (1.f + expf(-m));   // masses [B,1]
    }
    __syncthreads();
    if (t < IN_) {
        float v = dec_b2[t];
        #pragma unroll
        for (int hh = 0; hh < H_; hh++) v = fmaf(h[hh], dec_w2[hh * IN_ + t], v);
        g_rec[b * IN_ + t] = v;
    }
}

// ============================================================
// Broadcast rec[b,:] to all S rows. Value held in a register;
// pure coalesced STG.128 stream. grid (32 chunks, 32 b) x 300:
// each block writes 64 rows x 75 float4 (16 iters of 4 rows).
// ============================================================
__global__ void fill_k(float4* __restrict__ out4)
{
    const int t     = threadIdx.x;           // 0..299
    const int chunk = blockIdx.x;            // 0..31
    const int b     = blockIdx.y;            // 0..31
    const int col   = t % 75;
    const int rowi  = t / 75;                // 0..3
    const float4 val = __ldg(reinterpret_cast<const float4*>(g_rec) + b * 75 + col);
    size_t idx = ((size_t)b * S_ + chunk * 64 + rowi) * 75 + col;
    #pragma unroll 8
    for (int i = 0; i < 16; i++) {           // 16 * 4 rows = 64 rows
        out4[idx] = val;
        idx += 300;
    }
}

extern "C" void kernel_launch(void* const* d_in, const int* in_sizes, int n_in,
                              void* d_out, int out_size)
{
    const float* inputs = (const float*)d_in[0];
    const float* enc_w1 = (const float*)d_in[1];
    const float* enc_b1 = (const float*)d_in[2];
    const float* enc_w2 = (const float*)d_in[3];
    const float* enc_b2 = (const float*)d_in[4];
    const float* attr   = (const float*)d_in[5];
    const float* dec_w1 = (const float*)d_in[6];
    const float* dec_b1 = (const float*)d_in[7];
    const float* dec_w2 = (const float*)d_in[8];
    const float* dec_b2 = (const float*)d_in[9];
    const float* mass_w = (const float*)d_in[10];
    const float* mass_b = (const float*)d_in[11];
    float* out = (float*)d_out;

    gda_main<<<NBLK, 128>>>(inputs, enc_w1, enc_b1, enc_w2, enc_b2, attr);
    dec_k<<<B_, 320>>>(dec_w1, dec_b1, dec_w2, dec_b2, mass_w, mass_b, out);
    dim3 fg(32, 32);
    fill_k<<<fg, 300>>>(reinterpret_cast<float4*>(out + B_ * D_));
}

// round 9
// speedup vs baseline: 1.0300x; 1.0300x over previous
#include <cuda_runtime.h>
#include <cstdint>

#define B_   32
#define S_   2048
#define IN_  300
#define H_   16
#define D_   16
#define A_   64
#define NIT  20
#define GRAV 0.01f

#define NPTS  (B_ * S_)    // 65536
#define NBLK  128          // main blocks: 256 thr, 2 points/thread -> 512 pts/blk
#define TPB   256

typedef unsigned long long u64;

// ---- packed f32x2 helpers (sm_103a FFMA2 path) ----
__device__ __forceinline__ u64 pack2(float lo, float hi) {
    u64 r; asm("mov.b64 %0, {%1,%2};" : "=l"(r) : "f"(lo), "f"(hi)); return r;
}
__device__ __forceinline__ void unpack2(u64 v, float& lo, float& hi) {
    asm("mov.b64 {%0,%1}, %2;" : "=f"(lo), "=f"(hi) : "l"(v));
}
__device__ __forceinline__ u64 ffma2(u64 a, u64 b, u64 c) {
    u64 d; asm("fma.rn.f32x2 %0, %1, %2, %3;" : "=l"(d) : "l"(a), "l"(b), "l"(c)); return d;
}
__device__ __forceinline__ u64 fmul2(u64 a, u64 b) {
    u64 d; asm("mul.rn.f32x2 %0, %1, %2;" : "=l"(d) : "l"(a), "l"(b)); return d;
}
__device__ __forceinline__ float sqrt_ap(float x) {
    float r; asm("sqrt.approx.f32 %0, %1;" : "=f"(r) : "f"(x)); return r;
}
__device__ __forceinline__ float rcp_ap(float x) {
    float r; asm("rcp.approx.f32 %0, %1;" : "=f"(r) : "f"(x)); return r;
}

// ---- scratch (device globals: no allocs allowed) ----
__device__ float g_afp[NBLK * D_];   // per-block partial sums of final positions
__device__ float g_chgp[NBLK];       // per-block partial of squared last-iter deltas
__device__ float g_rec[B_ * IN_];    // decoder output per b

// encoder layer-1 step for one input scalar (both points share weights)
#define ENC4(xa, xb, w0, w1, w2, w3) do {                                   \
    u64 xa2 = pack2(xa, xa), xb2 = pack2(xb, xb);                           \
    accA[0]=ffma2(xa2,(w0).x,accA[0]); accB[0]=ffma2(xb2,(w0).x,accB[0]);   \
    accA[1]=ffma2(xa2,(w0).y,accA[1]); accB[1]=ffma2(xb2,(w0).y,accB[1]);   \
    accA[2]=ffma2(xa2,(w1).x,accA[2]); accB[2]=ffma2(xb2,(w1).x,accB[2]);   \
    accA[3]=ffma2(xa2,(w1).y,accA[3]); accB[3]=ffma2(xb2,(w1).y,accB[3]);   \
    accA[4]=ffma2(xa2,(w2).x,accA[4]); accB[4]=ffma2(xb2,(w2).x,accB[4]);   \
    accA[5]=ffma2(xa2,(w2).y,accA[5]); accB[5]=ffma2(xb2,(w2).y,accB[5]);   \
    accA[6]=ffma2(xa2,(w3).x,accA[6]); accB[6]=ffma2(xb2,(w3).x,accB[6]);   \
    accA[7]=ffma2(xa2,(w3).y,accA[7]); accB[7]=ffma2(xb2,(w3).y,accB[7]);   \
} while (0)

// ============================================================
// Fused: encoder + 20 gravity iterations + block reductions.
// 128 blocks x 256 threads (single wave, 8 warps/SM -> 2 warps
// per SMSP), TWO points per thread for ILP: 4 independent
// instruction streams per scheduler.
// ============================================================
__global__ void __launch_bounds__(TPB) gda_main(
    const float* __restrict__ inputs,
    const float* __restrict__ enc_w1, const float* __restrict__ enc_b1,
    const float* __restrict__ enc_w2, const float* __restrict__ enc_b2,
    const float* __restrict__ attractors)
{
    __shared__ ulonglong2 s_w1[IN_ * 4];   // 300x16 f32 = 19200B
    __shared__ ulonglong2 s_att[A_ * 4];   // 64x16 f32  = 4096B
    __shared__ float s_asq[A_];            // |a|^2
    __shared__ float s_b1[H_], s_b2[D_], s_w2[H_ * D_];
    __shared__ float s_af[D_];
    __shared__ float s_chg;

    const int tid = threadIdx.x;
    {
        float* w1f = reinterpret_cast<float*>(s_w1);
        for (int i = tid; i < IN_ * H_; i += TPB) w1f[i] = enc_w1[i];
        float* af = reinterpret_cast<float*>(s_att);
        for (int i = tid; i < A_ * D_; i += TPB) af[i] = attractors[i];
        for (int i = tid; i < H_ * D_; i += TPB) s_w2[i] = enc_w2[i];
        if (tid < H_)      s_b1[tid] = enc_b1[tid];
        if (tid < D_)      s_b2[tid] = enc_b2[tid];
        if (tid < D_)      s_af[tid] = 0.f;
        if (tid == 0)      s_chg = 0.f;
    }
    __syncthreads();
    if (tid < A_) {
        const float* a = reinterpret_cast<const float*>(s_att) + tid * D_;
        float q = 0.f;
        #pragma unroll
        for (int d = 0; d < D_; d++) q = fmaf(a[d], a[d], q);
        s_asq[tid] = q;
    }
    __syncthreads();

    const int pA = blockIdx.x * (2 * TPB) + tid;  // point A
    const int pB = pA + TPB;                      // point B

    // ---------------- encoder layer 1 (both points, shared weight loads) ----
    u64 accA[8], accB[8];
    #pragma unroll
    for (int j = 0; j < 8; j++) { accA[j] = 0ull; accB[j] = 0ull; }
    const float4* rowA = reinterpret_cast<const float4*>(inputs + (size_t)pA * IN_);
    const float4* rowB = reinterpret_cast<const float4*>(inputs + (size_t)pB * IN_);
    for (int i = 0; i < IN_ / 4; i++) {
        float4 xA = __ldg(rowA + i);
        float4 xB = __ldg(rowB + i);
        const ulonglong2* wp = s_w1 + i * 16;
        ENC4(xA.x, xB.x, wp[0],  wp[1],  wp[2],  wp[3]);
        ENC4(xA.y, xB.y, wp[4],  wp[5],  wp[6],  wp[7]);
        ENC4(xA.z, xB.z, wp[8],  wp[9],  wp[10], wp[11]);
        ENC4(xA.w, xB.w, wp[12], wp[13], wp[14], wp[15]);
    }

    // ---------------- encoder layer 2 (scalar, per point) ----------------
    u64 p2a[8], p2b[8];
    {
        float hvA[H_], hvB[H_];
        #pragma unroll
        for (int j = 0; j < 8; j++) {
            float lo, hi;
            unpack2(accA[j], lo, hi);
            hvA[2*j]   = fmaxf(lo + s_b1[2*j],   0.f);
            hvA[2*j+1] = fmaxf(hi + s_b1[2*j+1], 0.f);
            unpack2(accB[j], lo, hi);
            hvB[2*j]   = fmaxf(lo + s_b1[2*j],   0.f);
            hvB[2*j+1] = fmaxf(hi + s_b1[2*j+1], 0.f);
        }
        #pragma unroll
        for (int d = 0; d < D_; d += 2) {
            float a0 = s_b2[d], a1 = s_b2[d+1];
            float b0 = s_b2[d], b1 = s_b2[d+1];
            #pragma unroll
            for (int h = 0; h < H_; h++) {
                float w0 = s_w2[h * D_ + d], w1 = s_w2[h * D_ + d + 1];
                a0 = fmaf(hvA[h], w0, a0);  a1 = fmaf(hvA[h], w1, a1);
                b0 = fmaf(hvB[h], w0, b0);  b1 = fmaf(hvB[h], w1, b1);
            }
            p2a[d >> 1] = pack2(a0, a1);
            p2b[d >> 1] = pack2(b0, b1);
        }
    }

    // ---------------- gravity: 20 iterations, 2 points interleaved ----
    const u64 k01   = pack2(0.1f, 0.1f);
    const u64 kneg1 = pack2(-1.f, -1.f);
    float chg = 0.f;

    for (int it = 0; it < NIT; it++) {
        u64 qa = fmul2(p2a[0], p2a[0]);
        u64 qb = fmul2(p2b[0], p2b[0]);
        #pragma unroll
        for (int j = 1; j < 8; j++) {
            qa = ffma2(p2a[j], p2a[j], qa);
            qb = ffma2(p2b[j], p2b[j], qb);
        }
        float l0, h0, l1, h1;
        unpack2(qa, l0, h0); unpack2(qb, l1, h1);
        const float psqA = l0 + h0;
        const float psqB = l1 + h1;

        u64 faA[8], faB[8];
        #pragma unroll
        for (int j = 0; j < 8; j++) { faA[j] = 0ull; faB[j] = 0ull; }
        float wsA0 = 0.f, wsA1 = 0.f, wsB0 = 0.f, wsB1 = 0.f;

        #pragma unroll 2
        for (int a = 0; a < A_; a++) {
            const ulonglong2* av = s_att + a * 4;
            ulonglong2 v0 = av[0], v1 = av[1], v2 = av[2], v3 = av[3];
            // two independent 8-deep dot chains
            u64 dA = fmul2(p2a[0], v0.x);
            u64 dB = fmul2(p2b[0], v0.x);
            dA = ffma2(p2a[1], v0.y, dA);  dB = ffma2(p2b[1], v0.y, dB);
            dA = ffma2(p2a[2], v1.x, dA);  dB = ffma2(p2b[2], v1.x, dB);
            dA = ffma2(p2a[3], v1.y, dA);  dB = ffma2(p2b[3], v1.y, dB);
            dA = ffma2(p2a[4], v2.x, dA);  dB = ffma2(p2b[4], v2.x, dB);
            dA = ffma2(p2a[5], v2.y, dA);  dB = ffma2(p2b[5], v2.y, dB);
            dA = ffma2(p2a[6], v3.x, dA);  dB = ffma2(p2b[6], v3.x, dB);
            dA = ffma2(p2a[7], v3.y, dA);  dB = ffma2(p2b[7], v3.y, dB);
            float aql, aqh, bql, bqh;
            unpack2(dA, aql, aqh); unpack2(dB, bql, bqh);
            const float asq = s_asq[a];
            float sA = fmaf(-2.f, aql + aqh, psqA + asq);
            float sB = fmaf(-2.f, bql + bqh, psqB + asq);
            sA = fmaxf(sA, 1e-12f);
            sB = fmaxf(sB, 1e-12f);
            float distA = sqrt_ap(sA) + 1e-6f;        // EXACT validated form
            float distB = sqrt_ap(sB) + 1e-6f;
            float wA = GRAV * rcp_ap(distA * distA);
            float wB = GRAV * rcp_ap(distB * distB);
            if (a & 1) { wsA1 += wA; wsB1 += wB; } else { wsA0 += wA; wsB0 += wB; }
            u64 wvA = pack2(wA, wA), wvB = pack2(wB, wB);
            faA[0] = ffma2(wvA, v0.x, faA[0]);  faB[0] = ffma2(wvB, v0.x, faB[0]);
            faA[1] = ffma2(wvA, v0.y, faA[1]);  faB[1] = ffma2(wvB, v0.y, faB[1]);
            faA[2] = ffma2(wvA, v1.x, faA[2]);  faB[2] = ffma2(wvB, v1.x, faB[2]);
            faA[3] = ffma2(wvA, v1.y, faA[3]);  faB[3] = ffma2(wvB, v1.y, faB[3]);
            faA[4] = ffma2(wvA, v2.x, faA[4]);  faB[4] = ffma2(wvB, v2.x, faB[4]);
            faA[5] = ffma2(wvA, v2.y, faA[5]);  faB[5] = ffma2(wvB, v2.y, faB[5]);
            faA[6] = ffma2(wvA, v3.x, faA[6]);  faB[6] = ffma2(wvB, v3.x, faB[6]);
            faA[7] = ffma2(wvA, v3.y, faA[7]);  faB[7] = ffma2(wvB, v3.y, faB[7]);
        }

        const float cA = fmaf(-0.1f, wsA0 + wsA1, 1.0f);
        const float cB = fmaf(-0.1f, wsB0 + wsB1, 1.0f);
        const u64 c2A = pack2(cA, cA);
        const u64 c2B = pack2(cB, cB);
        if (it == NIT - 1) {
            u64 chA = 0ull, chB = 0ull;
            #pragma unroll
            for (int j = 0; j < 8; j++) {
                u64 npA = ffma2(p2a[j], c2A, fmul2(faA[j], k01));
                u64 npB = ffma2(p2b[j], c2B, fmul2(faB[j], k01));
                u64 dlA = ffma2(p2a[j], kneg1, npA);
                u64 dlB = ffma2(p2b[j], kneg1, npB);
                chA = ffma2(dlA, dlA, chA);
                chB = ffma2(dlB, dlB, chB);
                p2a[j] = npA;  p2b[j] = npB;
            }
            float cl, ch;
            unpack2(chA, cl, ch); chg  = cl + ch;
            unpack2(chB, cl, ch); chg += cl + ch;
        } else {
            #pragma unroll
            for (int j = 0; j < 8; j++) {
                p2a[j] = ffma2(p2a[j], c2A, fmul2(faA[j], k01));
                p2b[j] = ffma2(p2b[j], c2B, fmul2(faB[j], k01));
            }
        }
    }

    // ---------------- reductions (A+B combined per thread) ----------------
    #pragma unroll
    for (int j = 0; j < 8; j++) {
        float la, ha, lb, hb;
        unpack2(p2a[j], la, ha);
        unpack2(p2b[j], lb, hb);
        float lo = la + lb, hi = ha + hb;
        #pragma unroll
        for (int off = 16; off; off >>= 1) {
            lo += __shfl_down_sync(0xffffffffu, lo, off);
            hi += __shfl_down_sync(0xffffffffu, hi, off);
        }
        if ((tid & 31) == 0) {
            atomicAdd(&s_af[2 * j], lo);
            atomicAdd(&s_af[2 * j + 1], hi);
        }
    }
    #pragma unroll
    for (int off = 16; off; off >>= 1)
        chg += __shfl_down_sync(0xffffffffu, chg, off);
    if ((tid & 31) == 0) atomicAdd(&s_chg, chg);
    __syncthreads();

    if (tid < D_) g_afp[blockIdx.x * D_ + tid] = s_af[tid];
    if (tid == 0) g_chgp[blockIdx.x]           = s_chg;
}

// ============================================================
// Decoder: reduce block partials -> af -> relu(16) -> 300,
// masses, final_change. 32 blocks (one per batch), 320 threads.
// ============================================================
__global__ void dec_k(const float* __restrict__ dec_w1, const float* __restrict__ dec_b1,
                      const float* __restrict__ dec_w2, const float* __restrict__ dec_b2,
                      const float* __restrict__ mass_w, const float* __restrict__ mass_b,
                      float* __restrict__ out)
{
    __shared__ float af[D_], h[H_];
    const int b = blockIdx.x, t = threadIdx.x;
    const int blk0 = b * (NBLK / B_);          // 4 gda blocks per batch
    if (t < D_) {
        float v = 0.f;
        #pragma unroll
        for (int k = 0; k < NBLK / B_; k++)
            v += g_afp[(blk0 + k) * D_ + t];
        v *= (1.f / (float)S_);
        af[t] = v;
        out[b * D_ + t] = v;                   // attractor_field [B,16]
    }
    if (b == 0 && t >= 32 && t < 64) {
        const int lane = t - 32;
        float c = 0.f;
        for (int i = lane; i < NBLK; i += 32) c += g_chgp[i];
        #pragma unroll
        for (int off = 16; off; off >>= 1)
            c += __shfl_down_sync(0xffffffffu, c, off);
        if (lane == 0)
            out[B_ * D_ + B_ * S_ * IN_ + B_] = sqrtf(c);   // final_change
    }
    __syncthreads();
    if (t < H_) {
        float v = dec_b1[t];
        #pragma unroll
        for (int d = 0; d < D_; d++) v = fmaf(af[d], dec_w1[d * H_ + t], v);
        h[t] = fmaxf(v, 0.f);
    } else if (t == H_) {
        float m = mass_b[0];
        #pragma unroll
        for (int d = 0; d < D_; d++) m = fmaf(af[d], mass_w[d], m);
        out[B_ * D_ + B_ * S_ * IN_ + b] = 1.f / (1.f + expf(-m));   // masses [B,1]
    }
    __syncthreads();
    if (t < IN_) {
        float v = dec_b2[t];
        #pragma unroll
        for (int hh = 0; hh < H_; hh++) v = fmaf(h[hh], dec_w2[hh * IN_ + t], v);
        g_rec[b * IN_ + t] = v;
    }
}

// ============================================================
// Broadcast rec[b,:] to all S rows. Value held in a register;
// pure coalesced STG.128 stream. grid (32 chunks, 32 b) x 300:
// each block writes 64 rows x 75 float4 (16 iters of 4 rows).
// ============================================================
__global__ void fill_k(float4* __restrict__ out4)
{
    const int t     = threadIdx.x;           // 0..299
    const int chunk = blockIdx.x;            // 0..31
    const int b     = blockIdx.y;            // 0..31
    const int col   = t % 75;
    const int rowi  = t / 75;                // 0..3
    const float4 val = __ldg(reinterpret_cast<const float4*>(g_rec) + b * 75 + col);
    size_t idx = ((size_t)b * S_ + chunk * 64 + rowi) * 75 + col;
    #pragma unroll 8
    for (int i = 0; i < 16; i++) {           // 16 * 4 rows = 64 rows
        out4[idx] = val;
        idx += 300;
    }
}

extern "C" void kernel_launch(void* const* d_in, const int* in_sizes, int n_in,
                              void* d_out, int out_size)
{
    const float* inputs = (const float*)d_in[0];
    const float* enc_w1 = (const float*)d_in[1];
    const float* enc_b1 = (const float*)d_in[2];
    const float* enc_w2 = (const float*)d_in[3];
    const float* enc_b2 = (const float*)d_in[4];
    const float* attr   = (const float*)d_in[5];
    const float* dec_w1 = (const float*)d_in[6];
    const float* dec_b1 = (const float*)d_in[7];
    const float* dec_w2 = (const float*)d_in[8];
    const float* dec_b2 = (const float*)d_in[9];
    const float* mass_w = (const float*)d_in[10];
    const float* mass_b = (const float*)d_in[11];
    float* out = (float*)d_out;

    gda_main<<<NBLK, TPB>>>(inputs, enc_w1, enc_b1, enc_w2, enc_b2, attr);
    dec_k<<<B_, 320>>>(dec_w1, dec_b1, dec_w2, dec_b2, mass_w, mass_b, out);
    dim3 fg(32, 32);
    fill_k<<<fg, 300>>>(reinterpret_cast<float4*>(out + B_ * D_));
}

// round 10
// speedup vs baseline: 1.1833x; 1.1488x over previous
#include <cuda_runtime.h>
#include <cstdint>

#define B_   32
#define S_   2048
#define IN_  300
#define H_   16
#define D_   16
#define A_   64
#define NIT  20
#define GRAV 0.01f

#define NPTS  (B_ * S_)    // 65536
#define GBLK  128          // gravity blocks
#define GTPB  512          // gravity threads/block: 16 warps -> 4 per SMSP, 1 wave

typedef unsigned long long u64;

// ---- packed f32x2 helpers (sm_103a FFMA2 path) ----
__device__ __forceinline__ u64 pack2(float lo, float hi) {
    u64 r; asm("mov.b64 %0, {%1,%2};" : "=l"(r) : "f"(lo), "f"(hi)); return r;
}
__device__ __forceinline__ void unpack2(u64 v, float& lo, float& hi) {
    asm("mov.b64 {%0,%1}, %2;" : "=f"(lo), "=f"(hi) : "l"(v));
}
__device__ __forceinline__ u64 ffma2(u64 a, u64 b, u64 c) {
    u64 d; asm("fma.rn.f32x2 %0, %1, %2, %3;" : "=l"(d) : "l"(a), "l"(b), "l"(c)); return d;
}
__device__ __forceinline__ u64 fmul2(u64 a, u64 b) {
    u64 d; asm("mul.rn.f32x2 %0, %1, %2;" : "=l"(d) : "l"(a), "l"(b)); return d;
}
__device__ __forceinline__ float sqrt_ap(float x) {
    float r; asm("sqrt.approx.f32 %0, %1;" : "=f"(r) : "f"(x)); return r;
}
__device__ __forceinline__ float rcp_ap(float x) {
    float r; asm("rcp.approx.f32 %0, %1;" : "=f"(r) : "f"(x)); return r;
}

// ---- scratch (device globals: no allocs allowed) ----
__device__ u64   g_emb[NPTS * 8];    // encoder output, packed f32x2 (4 MB)
__device__ float g_afp[GBLK * D_];   // per-block partial sums of final positions
__device__ float g_chgp[GBLK];       // per-block partial of squared last-iter deltas
__device__ float g_rec[B_ * IN_];    // decoder output per b

// ============================================================
// Encoder: 300 -> 16 relu -> 16. One thread per point.
// (Validated verbatim in R5.)
// ============================================================
__global__ void __launch_bounds__(256) enc_k(
    const float* __restrict__ inputs,
    const float* __restrict__ enc_w1, const float* __restrict__ enc_b1,
    const float* __restrict__ enc_w2, const float* __restrict__ enc_b2)
{
    __shared__ ulonglong2 s_w1[IN_ * 4];   // 300x16 f32 = 19200B
    __shared__ float s_b1[H_], s_b2[D_], s_w2[H_ * D_];

    const int tid = threadIdx.x;
    {
        float* w1f = reinterpret_cast<float*>(s_w1);
        for (int i = tid; i < IN_ * H_; i += 256) w1f[i] = enc_w1[i];
        if (tid < H_)      s_b1[tid] = enc_b1[tid];
        if (tid < D_)      s_b2[tid] = enc_b2[tid];
        if (tid < H_ * D_) s_w2[tid] = enc_w2[tid];   // 256 threads cover 256
    }
    __syncthreads();

    const int p = blockIdx.x * 256 + tid;

    u64 acc2[8];
    #pragma unroll
    for (int j = 0; j < 8; j++) acc2[j] = 0ull;
    const float4* row = reinterpret_cast<const float4*>(inputs + (size_t)p * IN_);
    for (int i = 0; i < IN_ / 4; i++) {
        float4 x = __ldg(row + i);
        const ulonglong2* wp = s_w1 + i * 16;
        u64 xb;
        xb = pack2(x.x, x.x);
        acc2[0] = ffma2(xb, wp[0].x, acc2[0]);  acc2[1] = ffma2(xb, wp[0].y, acc2[1]);
        acc2[2] = ffma2(xb, wp[1].x, acc2[2]);  acc2[3] = ffma2(xb, wp[1].y, acc2[3]);
        acc2[4] = ffma2(xb, wp[2].x, acc2[4]);  acc2[5] = ffma2(xb, wp[2].y, acc2[5]);
        acc2[6] = ffma2(xb, wp[3].x, acc2[6]);  acc2[7] = ffma2(xb, wp[3].y, acc2[7]);
        xb = pack2(x.y, x.y);
        acc2[0] = ffma2(xb, wp[4].x, acc2[0]);  acc2[1] = ffma2(xb, wp[4].y, acc2[1]);
        acc2[2] = ffma2(xb, wp[5].x, acc2[2]);  acc2[3] = ffma2(xb, wp[5].y, acc2[3]);
        acc2[4] = ffma2(xb, wp[6].x, acc2[4]);  acc2[5] = ffma2(xb, wp[6].y, acc2[5]);
        acc2[6] = ffma2(xb, wp[7].x, acc2[6]);  acc2[7] = ffma2(xb, wp[7].y, acc2[7]);
        xb = pack2(x.z, x.z);
        acc2[0] = ffma2(xb, wp[8].x,  acc2[0]); acc2[1] = ffma2(xb, wp[8].y,  acc2[1]);
        acc2[2] = ffma2(xb, wp[9].x,  acc2[2]); acc2[3] = ffma2(xb, wp[9].y,  acc2[3]);
        acc2[4] = ffma2(xb, wp[10].x, acc2[4]); acc2[5] = ffma2(xb, wp[10].y, acc2[5]);
        acc2[6] = ffma2(xb, wp[11].x, acc2[6]); acc2[7] = ffma2(xb, wp[11].y, acc2[7]);
        xb = pack2(x.w, x.w);
        acc2[0] = ffma2(xb, wp[12].x, acc2[0]); acc2[1] = ffma2(xb, wp[12].y, acc2[1]);
        acc2[2] = ffma2(xb, wp[13].x, acc2[2]); acc2[3] = ffma2(xb, wp[13].y, acc2[3]);
        acc2[4] = ffma2(xb, wp[14].x, acc2[4]); acc2[5] = ffma2(xb, wp[14].y, acc2[5]);
        acc2[6] = ffma2(xb, wp[15].x, acc2[6]); acc2[7] = ffma2(xb, wp[15].y, acc2[7]);
    }

    float hv[H_];
    #pragma unroll
    for (int j = 0; j < 8; j++) {
        float lo, hi; unpack2(acc2[j], lo, hi);
        hv[2 * j]     = fmaxf(lo + s_b1[2 * j],     0.f);
        hv[2 * j + 1] = fmaxf(hi + s_b1[2 * j + 1], 0.f);
    }
    #pragma unroll
    for (int j = 0; j < 8; j++) {
        float v0 = s_b2[2 * j], v1 = s_b2[2 * j + 1];
        #pragma unroll
        for (int h = 0; h < H_; h++) {
            v0 = fmaf(hv[h], s_w2[h * D_ + 2 * j], v0);
            v1 = fmaf(hv[h], s_w2[h * D_ + 2 * j + 1], v1);
        }
        g_emb[(size_t)p * 8 + j] = pack2(v0, v1);
    }
}

// ============================================================
// Gravity: 20 iterations, ONE thread per point, R3-validated
// arithmetic verbatim. 128 blocks x 512 threads: 16 warps/SM
// (4 per SMSP), single perfectly-balanced wave; smem 4.5 KB.
// ============================================================
__global__ void __launch_bounds__(GTPB) grav_k(
    const float* __restrict__ attractors)
{
    __shared__ ulonglong2 s_att[A_ * 4];   // 64x16 f32 = 4096B
    __shared__ float s_asq[A_];            // |a|^2
    __shared__ float s_af[D_];
    __shared__ float s_chg;

    const int tid = threadIdx.x;
    {
        float* af = reinterpret_cast<float*>(s_att);
        for (int i = tid; i < A_ * D_; i += GTPB) af[i] = attractors[i];
        if (tid < D_) s_af[tid] = 0.f;
        if (tid == 0) s_chg = 0.f;
    }
    __syncthreads();
    if (tid < A_) {
        const float* a = reinterpret_cast<const float*>(s_att) + tid * D_;
        float q = 0.f;
        #pragma unroll
        for (int d = 0; d < D_; d++) q = fmaf(a[d], a[d], q);
        s_asq[tid] = q;
    }
    __syncthreads();

    const int point = blockIdx.x * GTPB + tid;

    u64 p2[8];
    {
        const ulonglong2* e = reinterpret_cast<const ulonglong2*>(g_emb + (size_t)point * 8);
        ulonglong2 e0 = e[0], e1 = e[1], e2 = e[2], e3 = e[3];
        p2[0] = e0.x; p2[1] = e0.y; p2[2] = e1.x; p2[3] = e1.y;
        p2[4] = e2.x; p2[5] = e2.y; p2[6] = e3.x; p2[7] = e3.y;
    }

    const u64 k01   = pack2(0.1f, 0.1f);
    const u64 kneg1 = pack2(-1.f, -1.f);
    float chg = 0.f;

    for (int it = 0; it < NIT; it++) {
        u64 q2 = fmul2(p2[0], p2[0]);
        #pragma unroll
        for (int j = 1; j < 8; j++) q2 = ffma2(p2[j], p2[j], q2);
        float plo, phi; unpack2(q2, plo, phi);
        const float psq = plo + phi;

        u64 fa2[8];
        #pragma unroll
        for (int j = 0; j < 8; j++) fa2[j] = 0ull;
        float wsum0 = 0.f, wsum1 = 0.f;

        #pragma unroll 4
        for (int a = 0; a < A_; a++) {
            const ulonglong2* av = s_att + a * 4;
            ulonglong2 v0 = av[0], v1 = av[1], v2 = av[2], v3 = av[3];
            u64 d2 = fmul2(p2[0], v0.x);
            d2 = ffma2(p2[1], v0.y, d2);
            d2 = ffma2(p2[2], v1.x, d2);
            d2 = ffma2(p2[3], v1.y, d2);
            d2 = ffma2(p2[4], v2.x, d2);
            d2 = ffma2(p2[5], v2.y, d2);
            d2 = ffma2(p2[6], v3.x, d2);
            d2 = ffma2(p2[7], v3.y, d2);
            float dl, dh; unpack2(d2, dl, dh);
            float s = fmaf(-2.f, dl + dh, psq + s_asq[a]);
            s = fmaxf(s, 1e-12f);
            float dist = sqrt_ap(s) + 1e-6f;          // EXACT validated form
            float w = GRAV * rcp_ap(dist * dist);
            if (a & 1) wsum1 += w; else wsum0 += w;
            u64 wv = pack2(w, w);
            fa2[0] = ffma2(wv, v0.x, fa2[0]);
            fa2[1] = ffma2(wv, v0.y, fa2[1]);
            fa2[2] = ffma2(wv, v1.x, fa2[2]);
            fa2[3] = ffma2(wv, v1.y, fa2[3]);
            fa2[4] = ffma2(wv, v2.x, fa2[4]);
            fa2[5] = ffma2(wv, v2.y, fa2[5]);
            fa2[6] = ffma2(wv, v3.x, fa2[6]);
            fa2[7] = ffma2(wv, v3.y, fa2[7]);
        }

        const float c = fmaf(-0.1f, wsum0 + wsum1, 1.0f);  // new_p = c*p + 0.1*fa
        const u64 c2 = pack2(c, c);
        if (it == NIT - 1) {
            u64 ch2 = 0ull;
            #pragma unroll
            for (int j = 0; j < 8; j++) {
                u64 np  = ffma2(p2[j], c2, fmul2(fa2[j], k01));
                u64 dlt = ffma2(p2[j], kneg1, np);         // np - p
                ch2 = ffma2(dlt, dlt, ch2);
                p2[j] = np;
            }
            float cl, ch; unpack2(ch2, cl, ch);
            chg = cl + ch;
        } else {
            #pragma unroll
            for (int j = 0; j < 8; j++)
                p2[j] = ffma2(p2[j], c2, fmul2(fa2[j], k01));
        }
    }

    // ---------------- reductions ----------------
    #pragma unroll
    for (int j = 0; j < 8; j++) {
        float lo, hi; unpack2(p2[j], lo, hi);
        #pragma unroll
        for (int off = 16; off; off >>= 1) {
            lo += __shfl_down_sync(0xffffffffu, lo, off);
            hi += __shfl_down_sync(0xffffffffu, hi, off);
        }
        if ((tid & 31) == 0) {
            atomicAdd(&s_af[2 * j], lo);
            atomicAdd(&s_af[2 * j + 1], hi);
        }
    }
    #pragma unroll
    for (int off = 16; off; off >>= 1)
        chg += __shfl_down_sync(0xffffffffu, chg, off);
    if ((tid & 31) == 0) atomicAdd(&s_chg, chg);
    __syncthreads();

    if (tid < D_) g_afp[blockIdx.x * D_ + tid] = s_af[tid];
    if (tid == 0) g_chgp[blockIdx.x]           = s_chg;
}

// ============================================================
// Decoder: reduce block partials -> af -> relu(16) -> 300,
// masses, final_change. 32 blocks (one per batch), 320 threads.
// ============================================================
__global__ void dec_k(const float* __restrict__ dec_w1, const float* __restrict__ dec_b1,
                      const float* __restrict__ dec_w2, const float* __restrict__ dec_b2,
                      const float* __restrict__ mass_w, const float* __restrict__ mass_b,
                      float* __restrict__ out)
{
    __shared__ float af[D_], h[H_];
    const int b = blockIdx.x, t = threadIdx.x;
    const int blk0 = b * (GBLK / B_);          // 4 gravity blocks per batch
    if (t < D_) {
        float v = 0.f;
        #pragma unroll
        for (int k = 0; k < GBLK / B_; k++)
            v += g_afp[(blk0 + k) * D_ + t];
        v *= (1.f / (float)S_);
        af[t] = v;
        out[b * D_ + t] = v;                   // attractor_field [B,16]
    }
    if (b == 0 && t >= 32 && t < 64) {
        const int lane = t - 32;
        float c = 0.f;
        for (int i = lane; i < GBLK; i += 32) c += g_chgp[i];
        #pragma unroll
        for (int off = 16; off; off >>= 1)
            c += __shfl_down_sync(0xffffffffu, c, off);
        if (lane == 0)
            out[B_ * D_ + B_ * S_ * IN_ + B_] = sqrtf(c);   // final_change
    }
    __syncthreads();
    if (t < H_) {
        float v = dec_b1[t];
        #pragma unroll
        for (int d = 0; d < D_; d++) v = fmaf(af[d], dec_w1[d * H_ + t], v);
        h[t] = fmaxf(v, 0.f);
    } else if (t == H_) {
        float m = mass_b[0];
        #pragma unroll
        for (int d = 0; d < D_; d++) m = fmaf(af[d], mass_w[d], m);
        out[B_ * D_ + B_ * S_ * IN_ + b] = 1.f / (1.f + expf(-m));   // masses [B,1]
    }
    __syncthreads();
    if (t < IN_) {
        float v = dec_b2[t];
        #pragma unroll
        for (int hh = 0; hh < H_; hh++) v = fmaf(h[hh], dec_w2[hh * IN_ + t], v);
        g_rec[b * IN_ + t] = v;
    }
}

// ============================================================
// Broadcast rec[b,:] to all S rows. Value held in a register;
// pure coalesced STG.128 stream.
// ============================================================
__global__ void fill_k(float4* __restrict__ out4)
{
    const int t     = threadIdx.x;           // 0..299
    const int chunk = blockIdx.x;            // 0..31
    const int b     = blockIdx.y;            // 0..31
    const int col   = t % 75;
    const int rowi  = t / 75;                // 0..3
    const float4 val = __ldg(reinterpret_cast<const float4*>(g_rec) + b * 75 + col);
    size_t idx = ((size_t)b * S_ + chunk * 64 + rowi) * 75 + col;
    #pragma unroll 8
    for (int i = 0; i < 16; i++) {           // 16 * 4 rows = 64 rows
        out4[idx] = val;
        idx += 300;
    }
}

extern "C" void kernel_launch(void* const* d_in, const int* in_sizes, int n_in,
                              void* d_out, int out_size)
{
    const float* inputs = (const float*)d_in[0];
    const float* enc_w1 = (const float*)d_in[1];
    const float* enc_b1 = (const float*)d_in[2];
    const float* enc_w2 = (const float*)d_in[3];
    const float* enc_b2 = (const float*)d_in[4];
    const float* attr   = (const float*)d_in[5];
    const float* dec_w1 = (const float*)d_in[6];
    const float* dec_b1 = (const float*)d_in[7];
    const float* dec_w2 = (const float*)d_in[8];
    const float* dec_b2 = (const float*)d_in[9];
    const float* mass_w = (const float*)d_in[10];
    const float* mass_b = (const float*)d_in[11];
    float* out = (float*)d_out;

    enc_k<<<NPTS / 256, 256>>>(inputs, enc_w1, enc_b1, enc_w2, enc_b2);
    grav_k<<<GBLK, GTPB>>>(attr);
    dec_k<<<B_, 320>>>(dec_w1, dec_b1, dec_w2, dec_b2, mass_w, mass_b, out);
    dim3 fg(32, 32);
    fill_k<<<fg, 300>>>(reinterpret_cast<float4*>(out + B_ * D_));
}

// round 11
// speedup vs baseline: 1.3137x; 1.1102x over previous
#include <cuda_runtime.h>
#include <cstdint>

#define B_   32
#define S_   2048
#define IN_  300
#define H_   16
#define D_   16
#define A_   64
#define NIT  20
#define GRAV 0.01f

#define NPTS  (B_ * S_)    // 65536
#define GBLK  128          // main blocks
#define GTPB  512          // threads/block: 16 warps/SM, 4/SMSP, single wave

typedef unsigned long long u64;

// ---- packed f32x2 helpers (sm_103a FFMA2 path) ----
__device__ __forceinline__ u64 pack2(float lo, float hi) {
    u64 r; asm("mov.b64 %0, {%1,%2};" : "=l"(r) : "f"(lo), "f"(hi)); return r;
}
__device__ __forceinline__ void unpack2(u64 v, float& lo, float& hi) {
    asm("mov.b64 {%0,%1}, %2;" : "=f"(lo), "=f"(hi) : "l"(v));
}
__device__ __forceinline__ u64 ffma2(u64 a, u64 b, u64 c) {
    u64 d; asm("fma.rn.f32x2 %0, %1, %2, %3;" : "=l"(d) : "l"(a), "l"(b), "l"(c)); return d;
}
__device__ __forceinline__ u64 fmul2(u64 a, u64 b) {
    u64 d; asm("mul.rn.f32x2 %0, %1, %2;" : "=l"(d) : "l"(a), "l"(b)); return d;
}
__device__ __forceinline__ float sqrt_ap(float x) {
    float r; asm("sqrt.approx.f32 %0, %1;" : "=f"(r) : "f"(x)); return r;
}
__device__ __forceinline__ float rcp_ap(float x) {
    float r; asm("rcp.approx.f32 %0, %1;" : "=f"(r) : "f"(x)); return r;
}

// ---- scratch (device globals: no allocs allowed) ----
__device__ float g_afp[GBLK * D_];   // per-block partial sums of final positions
__device__ float g_chgp[GBLK];       // per-block partial of squared last-iter deltas
__device__ float g_rec[B_ * IN_];    // decoder output per b

// ============================================================
// Fused: encoder (300->16 relu ->16) + 20 gravity iterations +
// block reductions. 128 blocks x 512 threads, ONE point/thread.
// Single perfectly-balanced wave; 4 warps per SMSP.
// Arithmetic verbatim from the R10-passing kernel.
// ============================================================
__global__ void __launch_bounds__(GTPB) gda_main(
    const float* __restrict__ inputs,
    const float* __restrict__ enc_w1, const float* __restrict__ enc_b1,
    const float* __restrict__ enc_w2, const float* __restrict__ enc_b2,
    const float* __restrict__ attractors)
{
    __shared__ ulonglong2 s_w1[IN_ * 4];   // 300x16 f32 = 19200B
    __shared__ ulonglong2 s_att[A_ * 4];   // 64x16 f32  = 4096B
    __shared__ float s_asq[A_];            // |a|^2
    __shared__ float s_b1[H_], s_b2[D_], s_w2[H_ * D_];
    __shared__ float s_af[D_];
    __shared__ float s_chg;

    const int tid = threadIdx.x;
    {
        float* w1f = reinterpret_cast<float*>(s_w1);
        for (int i = tid; i < IN_ * H_; i += GTPB) w1f[i] = enc_w1[i];
        float* af = reinterpret_cast<float*>(s_att);
        for (int i = tid; i < A_ * D_; i += GTPB) af[i] = attractors[i];
        for (int i = tid; i < H_ * D_; i += GTPB) s_w2[i] = enc_w2[i];
        if (tid < H_) s_b1[tid] = enc_b1[tid];
        if (tid < D_) s_b2[tid] = enc_b2[tid];
        if (tid < D_) s_af[tid] = 0.f;
        if (tid == 0) s_chg = 0.f;
    }
    __syncthreads();
    if (tid < A_) {
        const float* a = reinterpret_cast<const float*>(s_att) + tid * D_;
        float q = 0.f;
        #pragma unroll
        for (int d = 0; d < D_; d++) q = fmaf(a[d], a[d], q);
        s_asq[tid] = q;
    }
    __syncthreads();

    const int p = blockIdx.x * GTPB + tid;

    // ---------------- encoder layer 1 (packed f32x2) ----------------
    u64 acc2[8];
    #pragma unroll
    for (int j = 0; j < 8; j++) acc2[j] = 0ull;
    const float4* row = reinterpret_cast<const float4*>(inputs + (size_t)p * IN_);
    for (int i = 0; i < IN_ / 4; i++) {
        float4 x = __ldg(row + i);
        const ulonglong2* wp = s_w1 + i * 16;
        u64 xb;
        xb = pack2(x.x, x.x);
        acc2[0] = ffma2(xb, wp[0].x, acc2[0]);  acc2[1] = ffma2(xb, wp[0].y, acc2[1]);
        acc2[2] = ffma2(xb, wp[1].x, acc2[2]);  acc2[3] = ffma2(xb, wp[1].y, acc2[3]);
        acc2[4] = ffma2(xb, wp[2].x, acc2[4]);  acc2[5] = ffma2(xb, wp[2].y, acc2[5]);
        acc2[6] = ffma2(xb, wp[3].x, acc2[6]);  acc2[7] = ffma2(xb, wp[3].y, acc2[7]);
        xb = pack2(x.y, x.y);
        acc2[0] = ffma2(xb, wp[4].x, acc2[0]);  acc2[1] = ffma2(xb, wp[4].y, acc2[1]);
        acc2[2] = ffma2(xb, wp[5].x, acc2[2]);  acc2[3] = ffma2(xb, wp[5].y, acc2[3]);
        acc2[4] = ffma2(xb, wp[6].x, acc2[4]);  acc2[5] = ffma2(xb, wp[6].y, acc2[5]);
        acc2[6] = ffma2(xb, wp[7].x, acc2[6]);  acc2[7] = ffma2(xb, wp[7].y, acc2[7]);
        xb = pack2(x.z, x.z);
        acc2[0] = ffma2(xb, wp[8].x,  acc2[0]); acc2[1] = ffma2(xb, wp[8].y,  acc2[1]);
        acc2[2] = ffma2(xb, wp[9].x,  acc2[2]); acc2[3] = ffma2(xb, wp[9].y,  acc2[3]);
        acc2[4] = ffma2(xb, wp[10].x, acc2[4]); acc2[5] = ffma2(xb, wp[10].y, acc2[5]);
        acc2[6] = ffma2(xb, wp[11].x, acc2[6]); acc2[7] = ffma2(xb, wp[11].y, acc2[7]);
        xb = pack2(x.w, x.w);
        acc2[0] = ffma2(xb, wp[12].x, acc2[0]); acc2[1] = ffma2(xb, wp[12].y, acc2[1]);
        acc2[2] = ffma2(xb, wp[13].x, acc2[2]); acc2[3] = ffma2(xb, wp[13].y, acc2[3]);
        acc2[4] = ffma2(xb, wp[14].x, acc2[4]); acc2[5] = ffma2(xb, wp[14].y, acc2[5]);
        acc2[6] = ffma2(xb, wp[15].x, acc2[6]); acc2[7] = ffma2(xb, wp[15].y, acc2[7]);
    }

    // ---------------- encoder layer 2 ----------------
    u64 p2[8];
    {
        float hv[H_];
        #pragma unroll
        for (int j = 0; j < 8; j++) {
            float lo, hi; unpack2(acc2[j], lo, hi);
            hv[2 * j]     = fmaxf(lo + s_b1[2 * j],     0.f);
            hv[2 * j + 1] = fmaxf(hi + s_b1[2 * j + 1], 0.f);
        }
        #pragma unroll
        for (int j = 0; j < 8; j++) {
            float v0 = s_b2[2 * j], v1 = s_b2[2 * j + 1];
            #pragma unroll
            for (int h = 0; h < H_; h++) {
                v0 = fmaf(hv[h], s_w2[h * D_ + 2 * j], v0);
                v1 = fmaf(hv[h], s_w2[h * D_ + 2 * j + 1], v1);
            }
            p2[j] = pack2(v0, v1);
        }
    }

    // ---------------- gravity: 20 iterations ----------------
    const u64 k01   = pack2(0.1f, 0.1f);
    const u64 kneg1 = pack2(-1.f, -1.f);
    float chg = 0.f;

    for (int it = 0; it < NIT; it++) {
        u64 q2 = fmul2(p2[0], p2[0]);
        #pragma unroll
        for (int j = 1; j < 8; j++) q2 = ffma2(p2[j], p2[j], q2);
        float plo, phi; unpack2(q2, plo, phi);
        const float psq = plo + phi;

        u64 fa2[8];
        #pragma unroll
        for (int j = 0; j < 8; j++) fa2[j] = 0ull;
        float wsum0 = 0.f, wsum1 = 0.f;

        #pragma unroll 8
        for (int a = 0; a < A_; a++) {
            const ulonglong2* av = s_att + a * 4;
            ulonglong2 v0 = av[0], v1 = av[1], v2 = av[2], v3 = av[3];
            u64 d2 = fmul2(p2[0], v0.x);
            d2 = ffma2(p2[1], v0.y, d2);
            d2 = ffma2(p2[2], v1.x, d2);
            d2 = ffma2(p2[3], v1.y, d2);
            d2 = ffma2(p2[4], v2.x, d2);
            d2 = ffma2(p2[5], v2.y, d2);
            d2 = ffma2(p2[6], v3.x, d2);
            d2 = ffma2(p2[7], v3.y, d2);
            float dl, dh; unpack2(d2, dl, dh);
            float s = fmaf(-2.f, dl + dh, psq + s_asq[a]);
            s = fmaxf(s, 1e-12f);
            float dist = sqrt_ap(s) + 1e-6f;          // EXACT validated form
            float w = GRAV * rcp_ap(dist * dist);
            if (a & 1) wsum1 += w; else wsum0 += w;
            u64 wv = pack2(w, w);
            fa2[0] = ffma2(wv, v0.x, fa2[0]);
            fa2[1] = ffma2(wv, v0.y, fa2[1]);
            fa2[2] = ffma2(wv, v1.x, fa2[2]);
            fa2[3] = ffma2(wv, v1.y, fa2[3]);
            fa2[4] = ffma2(wv, v2.x, fa2[4]);
            fa2[5] = ffma2(wv, v2.y, fa2[5]);
            fa2[6] = ffma2(wv, v3.x, fa2[6]);
            fa2[7] = ffma2(wv, v3.y, fa2[7]);
        }

        const float c = fmaf(-0.1f, wsum0 + wsum1, 1.0f);  // new_p = c*p + 0.1*fa
        const u64 c2 = pack2(c, c);
        if (it == NIT - 1) {
            u64 ch2 = 0ull;
            #pragma unroll
            for (int j = 0; j < 8; j++) {
                u64 np  = ffma2(p2[j], c2, fmul2(fa2[j], k01));
                u64 dlt = ffma2(p2[j], kneg1, np);         // np - p
                ch2 = ffma2(dlt, dlt, ch2);
                p2[j] = np;
            }
            float cl, ch; unpack2(ch2, cl, ch);
            chg = cl + ch;
        } else {
            #pragma unroll
            for (int j = 0; j < 8; j++)
                p2[j] = ffma2(p2[j], c2, fmul2(fa2[j], k01));
        }
    }

    // ---------------- reductions ----------------
    #pragma unroll
    for (int j = 0; j < 8; j++) {
        float lo, hi; unpack2(p2[j], lo, hi);
        #pragma unroll
        for (int off = 16; off; off >>= 1) {
            lo += __shfl_down_sync(0xffffffffu, lo, off);
            hi += __shfl_down_sync(0xffffffffu, hi, off);
        }
        if ((tid & 31) == 0) {
            atomicAdd(&s_af[2 * j], lo);
            atomicAdd(&s_af[2 * j + 1], hi);
        }
    }
    #pragma unroll
    for (int off = 16; off; off >>= 1)
        chg += __shfl_down_sync(0xffffffffu, chg, off);
    if ((tid & 31) == 0) atomicAdd(&s_chg, chg);
    __syncthreads();

    if (tid < D_) g_afp[blockIdx.x * D_ + tid] = s_af[tid];
    if (tid == 0) g_chgp[blockIdx.x]           = s_chg;
}

// ============================================================
// Decoder: reduce block partials -> af -> relu(16) -> 300,
// masses, final_change. 32 blocks (one per batch), 320 threads.
// ============================================================
__global__ void dec_k(const float* __restrict__ dec_w1, const float* __restrict__ dec_b1,
                      const float* __restrict__ dec_w2, const float* __restrict__ dec_b2,
                      const float* __restrict__ mass_w, const float* __restrict__ mass_b,
                      float* __restrict__ out)
{
    __shared__ float af[D_], h[H_];
    const int b = blockIdx.x, t = threadIdx.x;
    const int blk0 = b * (GBLK / B_);          // 4 main blocks per batch
    if (t < D_) {
        float v = 0.f;
        #pragma unroll
        for (int k = 0; k < GBLK / B_; k++)
            v += g_afp[(blk0 + k) * D_ + t];
        v *= (1.f / (float)S_);
        af[t] = v;
        out[b * D_ + t] = v;                   // attractor_field [B,16]
    }
    if (b == 0 && t >= 32 && t < 64) {
        const int lane = t - 32;
        float c = 0.f;
        for (int i = lane; i < GBLK; i += 32) c += g_chgp[i];
        #pragma unroll
        for (int off = 16; off; off >>= 1)
            c += __shfl_down_sync(0xffffffffu, c, off);
        if (lane == 0)
            out[B_ * D_ + B_ * S_ * IN_ + B_] = sqrtf(c);   // final_change
    }
    __syncthreads();
    if (t < H_) {
        float v = dec_b1[t];
        #pragma unroll
        for (int d = 0; d < D_; d++) v = fmaf(af[d], dec_w1[d * H_ + t], v);
        h[t] = fmaxf(v, 0.f);
    } else if (t == H_) {
        float m = mass_b[0];
        #pragma unroll
        for (int d = 0; d < D_; d++) m = fmaf(af[d], mass_w[d], m);
        out[B_ * D_ + B_ * S_ * IN_ + b] = 1.f / (1.f + expf(-m));   // masses [B,1]
    }
    __syncthreads();
    if (t < IN_) {
        float v = dec_b2[t];
        #pragma unroll
        for (int hh = 0; hh < H_; hh++) v = fmaf(h[hh], dec_w2[hh * IN_ + t], v);
        g_rec[b * IN_ + t] = v;
    }
}

// ============================================================
// Broadcast rec[b,:] to all S rows. Value held in a register;
// pure coalesced STG.128 stream.
// ============================================================
__global__ void fill_k(float4* __restrict__ out4)
{
    const int t     = threadIdx.x;           // 0..299
    const int chunk = blockIdx.x;            // 0..31
    const int b     = blockIdx.y;            // 0..31
    const int col   = t % 75;
    const int rowi  = t / 75;                // 0..3
    const float4 val = __ldg(reinterpret_cast<const float4*>(g_rec) + b * 75 + col);
    size_t idx = ((size_t)b * S_ + chunk * 64 + rowi) * 75 + col;
    #pragma unroll 8
    for (int i = 0; i < 16; i++) {           // 16 * 4 rows = 64 rows
        out4[idx] = val;
        idx += 300;
    }
}

extern "C" void kernel_launch(void* const* d_in, const int* in_sizes, int n_in,
                              void* d_out, int out_size)
{
    const float* inputs = (const float*)d_in[0];
    const float* enc_w1 = (const float*)d_in[1];
    const float* enc_b1 = (const float*)d_in[2];
    const float* enc_w2 = (const float*)d_in[3];
    const float* enc_b2 = (const float*)d_in[4];
    const float* attr   = (const float*)d_in[5];
    const float* dec_w1 = (const float*)d_in[6];
    const float* dec_b1 = (const float*)d_in[7];
    const float* dec_w2 = (const float*)d_in[8];
    const float* dec_b2 = (const float*)d_in[9];
    const float* mass_w = (const float*)d_in[10];
    const float* mass_b = (const float*)d_in[11];
    float* out = (float*)d_out;

    gda_main<<<GBLK, GTPB>>>(inputs, enc_w1, enc_b1, enc_w2, enc_b2, attr);
    dec_k<<<B_, 320>>>(dec_w1, dec_b1, dec_w2, dec_b2, mass_w, mass_b, out);
    dim3 fg(32, 32);
    fill_k<<<fg, 300>>>(reinterpret_cast<float4*>(out + B_ * D_));
}